// round 15
// baseline (speedup 1.0000x reference)
#include <cuda_runtime.h>
#include <cuda_bf16.h>
#include <cuda_fp16.h>
#include <math_constants.h>
#include <cstdint>

// Shapes: latents [16,2048,512] -> [32768,512], embedding [8192,512]
constexpr int DDIM  = 512;
constexpr int KCODE = 8192;
constexpr int NROWS = 16 * 2048;

constexpr int TM = 128;
constexpr int TN = 128;
constexpr int KB = 64;           // bf16 elems per stage row = 128B
constexpr int NSTAGE = 3;
constexpr int NKS = DDIM / KB;   // 8
constexpr int NRT = NROWS / TM;  // 256
constexpr int NCT = KCODE / TN;  // 64

constexpr float MARGIN = 1.2e-3f; // bf16 worst (2.7e-4) + tie win (1.9e-4) + half ulp, 2x slack

constexpr uint32_t STAGE_BYTES = TM * KB * 2;               // 16384
constexpr uint32_t B_OFF       = NSTAGE * STAGE_BYTES;      // 49152
constexpr uint32_t SMEM_BYTES  = 2 * NSTAGE * STAGE_BYTES;  // 98304

// ---------------- scratch ----------------
__device__ __nv_bfloat16 g_Xb[NROWS * DDIM];
__device__ __nv_bfloat16 g_Eb[KCODE * DDIM];
__device__ float    g_e2[KCODE];
__device__ float    g_x2[NROWS];
__device__ __half   g_score[(size_t)NROWS * KCODE];   // 512 MB approx scores
__device__ unsigned g_rowmin[NROWS];                  // float-ordered keys
__device__ int      g_done[NRT];                      // col-tile completion counters

// ---------------- helpers ----------------
__device__ __forceinline__ uint32_t smem_u32(const void* p) {
    uint32_t a;
    asm("{ .reg .u64 t; cvta.to.shared.u64 t, %1; cvt.u32.u64 %0, t; }" : "=r"(a) : "l"(p));
    return a;
}
__device__ __forceinline__ unsigned fkey(float f) {          // order-preserving
    unsigned b = __float_as_uint(f);
    return b ^ (unsigned)(((int)b >> 31) | 0x80000000);
}
__device__ __forceinline__ float funkey(unsigned k) {
    unsigned b = k ^ (unsigned)((~(int)k >> 31) | 0x80000000);
    return __uint_as_float(b);
}
__device__ __forceinline__ void mma16(float* d, const uint32_t* a, const uint32_t* b) {
    asm volatile(
        "mma.sync.aligned.m16n8k16.row.col.f32.bf16.bf16.f32 "
        "{%0,%1,%2,%3}, {%4,%5,%6,%7}, {%8,%9}, {%0,%1,%2,%3};"
        : "+f"(d[0]), "+f"(d[1]), "+f"(d[2]), "+f"(d[3])
        : "r"(a[0]), "r"(a[1]), "r"(a[2]), "r"(a[3]), "r"(b[0]), "r"(b[1]));
}
#define LDSM_X4(r0, r1, r2, r3, addr)                                            \
    asm volatile("ldmatrix.sync.aligned.m8n8.x4.shared.b16 {%0,%1,%2,%3}, [%4];" \
        : "=r"(r0), "=r"(r1), "=r"(r2), "=r"(r3) : "r"(addr))
#define CP_ASYNC16(dst, src) \
    asm volatile("cp.async.cg.shared.global [%0], [%1], 16;" :: "r"(dst), "l"(src) : "memory")
#define CP_COMMIT()  asm volatile("cp.async.commit_group;" ::: "memory")
#define CP_WAIT1()   asm volatile("cp.async.wait_group 1;" ::: "memory")

// ---------------------------------------------------------------------------
// Kernel 1: norms (R1-proven structure) + bf16 convert + rowmin/done init
// ---------------------------------------------------------------------------
__global__ void prep_kernel(const float* __restrict__ X, const float* __restrict__ E) {
    int w    = (blockIdx.x * blockDim.x + threadIdx.x) >> 5;
    int lane = threadIdx.x & 31;
    if (w >= KCODE + NROWS) return;
    bool isE = (w < KCODE);
    int  r   = isE ? w : (w - KCODE);
    const float4* p = (const float4*)(isE ? (E + (size_t)r * DDIM) : (X + (size_t)r * DDIM));

    float s = 0.f;
#pragma unroll
    for (int i = 0; i < 4; i++) {
        float4 v = p[lane + 32 * i];
        s += v.x * v.x + v.y * v.y + v.z * v.z + v.w * v.w;
    }
#pragma unroll
    for (int o = 16; o > 0; o >>= 1) s += __shfl_xor_sync(0xffffffffu, s, o);
    if (lane == 0) {
        if (isE) g_e2[r] = s;
        else {
            g_x2[r] = s;
            g_rowmin[r] = 0xFFFFFFFFu;
            if ((r & (TM - 1)) == 0) g_done[r / TM] = 0;
        }
    }

    __nv_bfloat162* dst = (__nv_bfloat162*)((isE ? g_Eb : g_Xb) + (size_t)r * DDIM);
#pragma unroll
    for (int i = 0; i < 4; i++) {
        float4 v = p[lane + 32 * i];
        dst[(lane + 32 * i) * 2 + 0] = __floats2bfloat162_rn(v.x, v.y);
        dst[(lane + 32 * i) * 2 + 1] = __floats2bfloat162_rn(v.z, v.w);
    }
}

// ---------------------------------------------------------------------------
// Kernel 2: bf16 GEMM (128x128 tile, K=512) via ldmatrix + mma.sync.
// Epilogue: fp16 score store + exact fp32 rowmin atomicMin (R7-identical),
// then last-CTA-per-row-block runs the rescue + gather/STE INLINE, overlapped
// with the remaining GEMM CTAs (threadFenceReduction pattern).
// ---------------------------------------------------------------------------
__global__ __launch_bounds__(256, 2) void vq_mma_kernel(
    const float* __restrict__ X, const float* __restrict__ E,
    float* __restrict__ out) {
    extern __shared__ char smem[];
    const uint32_t sb = smem_u32(smem);
    const int tid = threadIdx.x;
    const int wid = tid >> 5, lane = tid & 31;
    const int g = lane >> 2, tig = lane & 3;
    const int wm = wid & 3, wn = wid >> 2;          // warp grid 4 x 2
    const int rt = blockIdx.x >> 6;                 // col-tile fastest (L2 reuse)
    const int ct = blockIdx.x & 63;
    const int row0 = rt * TM;
    const int col0 = ct * TN;

    auto stage_cp = [&](int s, int ks) {
#pragma unroll
        for (int i = 0; i < 4; i++) {               // A: 1024 16B chunks
            int u = tid + 256 * i, row = u >> 3, c = u & 7;
            const void* src = g_Xb + (size_t)(row0 + row) * DDIM + ks + c * 8;
            uint32_t dst = sb + (uint32_t)s * STAGE_BYTES +
                           (uint32_t)(row * 128 + (c ^ (row & 7)) * 16);
            CP_ASYNC16(dst, src);
        }
#pragma unroll
        for (int i = 0; i < 4; i++) {               // B: 1024 16B chunks
            int u = tid + 256 * i, row = u >> 3, c = u & 7;
            const void* src = g_Eb + (size_t)(col0 + row) * DDIM + ks + c * 8;
            uint32_t dst = sb + B_OFF + (uint32_t)s * STAGE_BYTES +
                           (uint32_t)(row * 128 + (c ^ (row & 7)) * 16);
            CP_ASYNC16(dst, src);
        }
    };

    const int lrow = lane & 7, sel = lane >> 3;
    int arow[2]; const int acb = sel >> 1;
#pragma unroll
    for (int mt = 0; mt < 2; mt++) arow[mt] = wm * 32 + mt * 16 + lrow + (sel & 1) * 8;
    int brow[4]; const int bcb = sel & 1;
#pragma unroll
    for (int ntp = 0; ntp < 4; ntp++) brow[ntp] = wn * 64 + ntp * 16 + (sel >> 1) * 8 + lrow;

    float acc[2][8][4];
#pragma unroll
    for (int mt = 0; mt < 2; mt++)
#pragma unroll
        for (int nt = 0; nt < 8; nt++)
#pragma unroll
            for (int q = 0; q < 4; q++) acc[mt][nt][q] = 0.f;

    stage_cp(0, 0);  CP_COMMIT();
    stage_cp(1, KB); CP_COMMIT();

    for (int ks = 0; ks < NKS; ks++) {
        CP_WAIT1();
        __syncthreads();
        if (ks < NKS - 2) stage_cp((ks + 2) % NSTAGE, (ks + 2) * KB);
        CP_COMMIT();

        const int buf = ks % NSTAGE;
        const uint32_t As = sb + (uint32_t)buf * STAGE_BYTES;
        const uint32_t Bs = sb + B_OFF + (uint32_t)buf * STAGE_BYTES;

#pragma unroll
        for (int s16 = 0; s16 < 4; s16++) {
            uint32_t a[2][4];
#pragma unroll
            for (int mt = 0; mt < 2; mt++) {
                int c = 2 * s16 + acb;
                uint32_t ad = As + arow[mt] * 128 + ((c ^ (arow[mt] & 7)) * 16);
                LDSM_X4(a[mt][0], a[mt][1], a[mt][2], a[mt][3], ad);
            }
            uint32_t b[8][2];
#pragma unroll
            for (int ntp = 0; ntp < 4; ntp++) {
                int c = 2 * s16 + bcb;
                uint32_t bd = Bs + brow[ntp] * 128 + ((c ^ (brow[ntp] & 7)) * 16);
                LDSM_X4(b[2 * ntp][0], b[2 * ntp][1], b[2 * ntp + 1][0], b[2 * ntp + 1][1], bd);
            }
#pragma unroll
            for (int nt = 0; nt < 8; nt++) {
                mma16(acc[0][nt], a[0], b[nt]);
                mma16(acc[1][nt], a[1], b[nt]);
            }
        }
    }

    // ---- epilogue: score = e2 - 2*dot -> fp16 store + per-row atomic min ----
#pragma unroll
    for (int mt = 0; mt < 2; mt++) {
#pragma unroll
        for (int rr = 0; rr < 2; rr++) {
            int row = row0 + wm * 32 + mt * 16 + g + rr * 8;
            __half* srow = g_score + ((size_t)row << 13);
            float rmin = CUDART_INF_F;
#pragma unroll
            for (int nt = 0; nt < 8; nt++) {
                int col = col0 + wn * 64 + nt * 8 + 2 * tig;
                float s0 = __ldg(&g_e2[col])     - 2.0f * acc[mt][nt][rr * 2];
                float s1 = __ldg(&g_e2[col + 1]) - 2.0f * acc[mt][nt][rr * 2 + 1];
                rmin = fminf(rmin, fminf(s0, s1));
                *(__half2*)(srow + col) = __floats2half2_rn(s0, s1);
            }
            rmin = fminf(rmin, __shfl_xor_sync(0xffffffffu, rmin, 1));
            rmin = fminf(rmin, __shfl_xor_sync(0xffffffffu, rmin, 2));
            if (tig == 0) atomicMin(&g_rowmin[row], fkey(rmin));
        }
    }

    // ---- last-CTA-per-row-block: inline rescue + gather/STE (overlapped) ----
    __shared__ int s_last;
    __threadfence();                                 // publish scores + rowmin
    __syncthreads();                                 // all epilogue stores issued
    if (tid == 0) s_last = (atomicAdd(&g_done[rt], 1) == NCT - 1);
    __syncthreads();
    if (!s_last) return;
    __threadfence();                                 // acquire others' stores

    for (int r = wid; r < TM; r += 8) {              // one warp per row, 16 rows/warp
        const int row = row0 + r;
        const uint4* sv = (const uint4*)(g_score + ((size_t)row << 13));
        const float Tf = funkey(g_rowmin[row]) + MARGIN;
        const float x2v = g_x2[row];
        const float* xr = X + (size_t)row * DDIM;
        unsigned long long best = ~0ull;

        for (int it = 0; it < 32; it++) {
            uint4 v = __ldg(&sv[lane + 32 * it]);
            __half2 h0 = *(__half2*)&v.x, h1 = *(__half2*)&v.y;
            __half2 h2 = *(__half2*)&v.z, h3 = *(__half2*)&v.w;
            __half2 mn2 = __hmin2(__hmin2(h0, h1), __hmin2(h2, h3));
            float mn = fminf(__low2float(mn2), __high2float(mn2));
            if (mn <= Tf) {                          // rare: ~1 hit / row
                const __half2 hh[4] = {h0, h1, h2, h3};
#pragma unroll
                for (int q = 0; q < 4; q++) {
                    float2 f = __half22float2(hh[q]);
                    float sc2[2] = {f.x, f.y};
#pragma unroll
                    for (int e = 0; e < 2; e++) {
                        if (sc2[e] <= Tf) {
                            int k = (lane + 32 * it) * 8 + q * 2 + e;
                            const float* er = E + (size_t)k * DDIM;
                            float accd = 0.f;
                            for (int d = 0; d < DDIM; d++) accd += xr[d] * er[d];
                            float t    = x2v + g_e2[k];
                            float dist = t - 2.0f * accd;   // exact R1-form dist
                            unsigned long long p =
                                ((unsigned long long)__float_as_uint(dist) << 32) | (unsigned)k;
                            best = (p < best) ? p : best;
                        }
                    }
                }
            }
        }
#pragma unroll
        for (int o = 16; o > 0; o >>= 1) {
            unsigned long long q = __shfl_xor_sync(0xffffffffu, best, o);
            best = (q < best) ? q : best;
        }
        const int c = (int)(unsigned)(best & 0xffffffffull);

        // fused gather + STE rounding: out = x + (e - x)
        const float4* ep = (const float4*)(E + (size_t)c * DDIM);
        const float4* xp = (const float4*)xr;
        float4* op = (float4*)(out + (size_t)row * DDIM);
#pragma unroll
        for (int i = 0; i < 4; i++) {
            float4 e = ep[lane + 32 * i];
            float4 x = xp[lane + 32 * i];
            float4 o;
            o.x = __fadd_rn(x.x, __fsub_rn(e.x, x.x));
            o.y = __fadd_rn(x.y, __fsub_rn(e.y, x.y));
            o.z = __fadd_rn(x.z, __fsub_rn(e.z, x.z));
            o.w = __fadd_rn(x.w, __fsub_rn(e.w, x.w));
            op[lane + 32 * i] = o;
        }
    }
}

// ---------------------------------------------------------------------------
extern "C" void kernel_launch(void* const* d_in, const int* in_sizes, int n_in,
                              void* d_out, int out_size) {
    const float* X = (const float*)d_in[0];
    const float* E = (const float*)d_in[1];
    float* out = (float*)d_out;

    cudaFuncSetAttribute(vq_mma_kernel, cudaFuncAttributeMaxDynamicSharedMemorySize,
                         SMEM_BYTES);

    int warps = KCODE + NROWS;
    prep_kernel<<<(warps * 32 + 255) / 256, 256>>>(X, E);
    vq_mma_kernel<<<NRT * NCT, 256, SMEM_BYTES>>>(X, E, out);
}

// round 16
// speedup vs baseline: 1.3631x; 1.3631x over previous
#include <cuda_runtime.h>
#include <cuda_bf16.h>
#include <cuda_fp16.h>
#include <math_constants.h>
#include <cstdint>

// Shapes: latents [16,2048,512] -> [32768,512], embedding [8192,512]
constexpr int DDIM  = 512;
constexpr int KCODE = 8192;
constexpr int NROWS = 16 * 2048;

constexpr int TM = 128;
constexpr int TN = 128;
constexpr int KB = 64;           // bf16 elems per stage row = 128B
constexpr int NSTAGE = 3;
constexpr int NKS = DDIM / KB;   // 8
constexpr int NCT = KCODE / TN;  // 64

constexpr int NCHUNK_PIPE = 4;                    // row-chunk pipeline depth
constexpr int ROWS_PER_CHUNK = NROWS / NCHUNK_PIPE;   // 8192
constexpr int RT_PER_CHUNK = ROWS_PER_CHUNK / TM;     // 64

constexpr float MARGIN = 1.2e-3f; // bf16 worst (2.7e-4) + tie win (1.9e-4) + half ulp, 2x slack

constexpr uint32_t STAGE_BYTES = TM * KB * 2;               // 16384
constexpr uint32_t B_OFF       = NSTAGE * STAGE_BYTES;      // 49152
constexpr uint32_t SMEM_BYTES  = 2 * NSTAGE * STAGE_BYTES;  // 98304

// ---------------- scratch ----------------
__device__ __nv_bfloat16 g_Xb[NROWS * DDIM];
__device__ __nv_bfloat16 g_Eb[KCODE * DDIM];
__device__ float    g_e2[KCODE];
__device__ float    g_x2[NROWS];
__device__ __half   g_score[(size_t)NROWS * KCODE];   // 512 MB approx scores
__device__ unsigned g_rowmin[NROWS];                  // float-ordered keys

// ---------------- helpers ----------------
__device__ __forceinline__ uint32_t smem_u32(const void* p) {
    uint32_t a;
    asm("{ .reg .u64 t; cvta.to.shared.u64 t, %1; cvt.u32.u64 %0, t; }" : "=r"(a) : "l"(p));
    return a;
}
__device__ __forceinline__ unsigned fkey(float f) {          // order-preserving
    unsigned b = __float_as_uint(f);
    return b ^ (unsigned)(((int)b >> 31) | 0x80000000);
}
__device__ __forceinline__ float funkey(unsigned k) {
    unsigned b = k ^ (unsigned)((~(int)k >> 31) | 0x80000000);
    return __uint_as_float(b);
}
__device__ __forceinline__ void mma16(float* d, const uint32_t* a, const uint32_t* b) {
    asm volatile(
        "mma.sync.aligned.m16n8k16.row.col.f32.bf16.bf16.f32 "
        "{%0,%1,%2,%3}, {%4,%5,%6,%7}, {%8,%9}, {%0,%1,%2,%3};"
        : "+f"(d[0]), "+f"(d[1]), "+f"(d[2]), "+f"(d[3])
        : "r"(a[0]), "r"(a[1]), "r"(a[2]), "r"(a[3]), "r"(b[0]), "r"(b[1]));
}
#define LDSM_X4(r0, r1, r2, r3, addr)                                            \
    asm volatile("ldmatrix.sync.aligned.m8n8.x4.shared.b16 {%0,%1,%2,%3}, [%4];" \
        : "=r"(r0), "=r"(r1), "=r"(r2), "=r"(r3) : "r"(addr))
#define CP_ASYNC16(dst, src) \
    asm volatile("cp.async.cg.shared.global [%0], [%1], 16;" :: "r"(dst), "l"(src) : "memory")
#define CP_COMMIT()  asm volatile("cp.async.commit_group;" ::: "memory")
#define CP_WAIT1()   asm volatile("cp.async.wait_group 1;" ::: "memory")

// ---------------------------------------------------------------------------
// Kernel 1: norms (R1-proven structure) + bf16 convert + rowmin init
// ---------------------------------------------------------------------------
__global__ void prep_kernel(const float* __restrict__ X, const float* __restrict__ E) {
    int w    = (blockIdx.x * blockDim.x + threadIdx.x) >> 5;
    int lane = threadIdx.x & 31;
    if (w >= KCODE + NROWS) return;
    bool isE = (w < KCODE);
    int  r   = isE ? w : (w - KCODE);
    const float4* p = (const float4*)(isE ? (E + (size_t)r * DDIM) : (X + (size_t)r * DDIM));

    float s = 0.f;
#pragma unroll
    for (int i = 0; i < 4; i++) {
        float4 v = p[lane + 32 * i];
        s += v.x * v.x + v.y * v.y + v.z * v.z + v.w * v.w;
    }
#pragma unroll
    for (int o = 16; o > 0; o >>= 1) s += __shfl_xor_sync(0xffffffffu, s, o);
    if (lane == 0) {
        if (isE) g_e2[r] = s;
        else { g_x2[r] = s; g_rowmin[r] = 0xFFFFFFFFu; }
    }

    __nv_bfloat162* dst = (__nv_bfloat162*)((isE ? g_Eb : g_Xb) + (size_t)r * DDIM);
#pragma unroll
    for (int i = 0; i < 4; i++) {
        float4 v = p[lane + 32 * i];
        dst[(lane + 32 * i) * 2 + 0] = __floats2bfloat162_rn(v.x, v.y);
        dst[(lane + 32 * i) * 2 + 1] = __floats2bfloat162_rn(v.z, v.w);
    }
}

// ---------------------------------------------------------------------------
// Kernel 2: bf16 GEMM (128x128 tile, K=512) via ldmatrix + mma.sync.
// Identical to the best-measured R7 kernel, + row_base chunk offset.
// ---------------------------------------------------------------------------
__global__ __launch_bounds__(256, 2) void vq_mma_kernel(int row_base) {
    extern __shared__ char smem[];
    const uint32_t sb = smem_u32(smem);
    const int tid = threadIdx.x;
    const int wid = tid >> 5, lane = tid & 31;
    const int g = lane >> 2, tig = lane & 3;
    const int wm = wid & 3, wn = wid >> 2;          // warp grid 4 x 2
    const int rt = blockIdx.x >> 6;                 // col-tile fastest (L2 reuse)
    const int ct = blockIdx.x & 63;
    const int row0 = row_base + rt * TM;
    const int col0 = ct * TN;

    auto stage_cp = [&](int s, int ks) {
#pragma unroll
        for (int i = 0; i < 4; i++) {               // A: 1024 16B chunks
            int u = tid + 256 * i, row = u >> 3, c = u & 7;
            const void* src = g_Xb + (size_t)(row0 + row) * DDIM + ks + c * 8;
            uint32_t dst = sb + (uint32_t)s * STAGE_BYTES +
                           (uint32_t)(row * 128 + (c ^ (row & 7)) * 16);
            CP_ASYNC16(dst, src);
        }
#pragma unroll
        for (int i = 0; i < 4; i++) {               // B: 1024 16B chunks
            int u = tid + 256 * i, row = u >> 3, c = u & 7;
            const void* src = g_Eb + (size_t)(col0 + row) * DDIM + ks + c * 8;
            uint32_t dst = sb + B_OFF + (uint32_t)s * STAGE_BYTES +
                           (uint32_t)(row * 128 + (c ^ (row & 7)) * 16);
            CP_ASYNC16(dst, src);
        }
    };

    const int lrow = lane & 7, sel = lane >> 3;
    int arow[2]; const int acb = sel >> 1;
#pragma unroll
    for (int mt = 0; mt < 2; mt++) arow[mt] = wm * 32 + mt * 16 + lrow + (sel & 1) * 8;
    int brow[4]; const int bcb = sel & 1;
#pragma unroll
    for (int ntp = 0; ntp < 4; ntp++) brow[ntp] = wn * 64 + ntp * 16 + (sel >> 1) * 8 + lrow;

    float acc[2][8][4];
#pragma unroll
    for (int mt = 0; mt < 2; mt++)
#pragma unroll
        for (int nt = 0; nt < 8; nt++)
#pragma unroll
            for (int q = 0; q < 4; q++) acc[mt][nt][q] = 0.f;

    stage_cp(0, 0);  CP_COMMIT();
    stage_cp(1, KB); CP_COMMIT();

    for (int ks = 0; ks < NKS; ks++) {
        CP_WAIT1();
        __syncthreads();
        if (ks < NKS - 2) stage_cp((ks + 2) % NSTAGE, (ks + 2) * KB);
        CP_COMMIT();

        const int buf = ks % NSTAGE;
        const uint32_t As = sb + (uint32_t)buf * STAGE_BYTES;
        const uint32_t Bs = sb + B_OFF + (uint32_t)buf * STAGE_BYTES;

#pragma unroll
        for (int s16 = 0; s16 < 4; s16++) {
            uint32_t a[2][4];
#pragma unroll
            for (int mt = 0; mt < 2; mt++) {
                int c = 2 * s16 + acb;
                uint32_t ad = As + arow[mt] * 128 + ((c ^ (arow[mt] & 7)) * 16);
                LDSM_X4(a[mt][0], a[mt][1], a[mt][2], a[mt][3], ad);
            }
            uint32_t b[8][2];
#pragma unroll
            for (int ntp = 0; ntp < 4; ntp++) {
                int c = 2 * s16 + bcb;
                uint32_t bd = Bs + brow[ntp] * 128 + ((c ^ (brow[ntp] & 7)) * 16);
                LDSM_X4(b[2 * ntp][0], b[2 * ntp][1], b[2 * ntp + 1][0], b[2 * ntp + 1][1], bd);
            }
#pragma unroll
            for (int nt = 0; nt < 8; nt++) {
                mma16(acc[0][nt], a[0], b[nt]);
                mma16(acc[1][nt], a[1], b[nt]);
            }
        }
    }

    // ---- epilogue: score = e2 - 2*dot -> fp16 store + per-row atomic min ----
#pragma unroll
    for (int mt = 0; mt < 2; mt++) {
#pragma unroll
        for (int rr = 0; rr < 2; rr++) {
            int row = row0 + wm * 32 + mt * 16 + g + rr * 8;
            __half* srow = g_score + ((size_t)row << 13);
            float rmin = CUDART_INF_F;
#pragma unroll
            for (int nt = 0; nt < 8; nt++) {
                int col = col0 + wn * 64 + nt * 8 + 2 * tig;
                float s0 = __ldg(&g_e2[col])     - 2.0f * acc[mt][nt][rr * 2];
                float s1 = __ldg(&g_e2[col + 1]) - 2.0f * acc[mt][nt][rr * 2 + 1];
                rmin = fminf(rmin, fminf(s0, s1));
                *(__half2*)(srow + col) = __floats2half2_rn(s0, s1);
            }
            rmin = fminf(rmin, __shfl_xor_sync(0xffffffffu, rmin, 1));
            rmin = fminf(rmin, __shfl_xor_sync(0xffffffffu, rmin, 2));
            if (tig == 0) atomicMin(&g_rowmin[row], fkey(rmin));
        }
    }
}

// ---------------------------------------------------------------------------
// Kernel 3: single-pass rescue + fused gather/STE (R7-identical) + row_base.
// One warp per row; exact dist form byte-identical to the proven path.
// ---------------------------------------------------------------------------
__global__ __launch_bounds__(256) void rescue_gather_kernel(
    const float* __restrict__ X, const float* __restrict__ E,
    float* __restrict__ out, int row_base) {
    int w    = (blockIdx.x * blockDim.x + threadIdx.x) >> 5;
    int lane = threadIdx.x & 31;
    if (w >= ROWS_PER_CHUNK) return;
    const int row = row_base + w;
    const uint4* sv = (const uint4*)(g_score + ((size_t)row << 13));
    const float Tf = funkey(g_rowmin[row]) + MARGIN;

    const float x2v = g_x2[row];
    const float* xr = X + (size_t)row * DDIM;
    unsigned long long best = ~0ull;

    for (int it = 0; it < 32; it++) {
        uint4 v = __ldg(&sv[lane + 32 * it]);
        __half2 h0 = *(__half2*)&v.x, h1 = *(__half2*)&v.y;
        __half2 h2 = *(__half2*)&v.z, h3 = *(__half2*)&v.w;
        __half2 mn2 = __hmin2(__hmin2(h0, h1), __hmin2(h2, h3));
        float mn = fminf(__low2float(mn2), __high2float(mn2));
        if (mn <= Tf) {                               // rare: ~1 hit / row
            const __half2 hh[4] = {h0, h1, h2, h3};
#pragma unroll
            for (int q = 0; q < 4; q++) {
                float2 f = __half22float2(hh[q]);
                float sc2[2] = {f.x, f.y};
#pragma unroll
                for (int e = 0; e < 2; e++) {
                    if (sc2[e] <= Tf) {
                        int k = (lane + 32 * it) * 8 + q * 2 + e;
                        const float* er = E + (size_t)k * DDIM;
                        float acc = 0.f;
                        for (int d = 0; d < DDIM; d++) acc += xr[d] * er[d];
                        float t    = x2v + g_e2[k];
                        float dist = t - 2.0f * acc;   // exact R1-form dist
                        unsigned long long p =
                            ((unsigned long long)__float_as_uint(dist) << 32) | (unsigned)k;
                        best = (p < best) ? p : best;
                    }
                }
            }
        }
    }
#pragma unroll
    for (int o = 16; o > 0; o >>= 1) {
        unsigned long long q = __shfl_xor_sync(0xffffffffu, best, o);
        best = (q < best) ? q : best;
    }
    const int c = (int)(unsigned)(best & 0xffffffffull);

    // fused gather + STE rounding: out = x + (e - x)
    const float4* ep = (const float4*)(E + (size_t)c * DDIM);
    const float4* xp = (const float4*)xr;
    float4* op = (float4*)(out + (size_t)row * DDIM);
#pragma unroll
    for (int i = 0; i < 4; i++) {
        float4 e = ep[lane + 32 * i];
        float4 x = xp[lane + 32 * i];
        float4 o;
        o.x = __fadd_rn(x.x, __fsub_rn(e.x, x.x));
        o.y = __fadd_rn(x.y, __fsub_rn(e.y, x.y));
        o.z = __fadd_rn(x.z, __fsub_rn(e.z, x.z));
        o.w = __fadd_rn(x.w, __fsub_rn(e.w, x.w));
        op[lane + 32 * i] = o;
    }
}

// ---------------------------------------------------------------------------
// Chunked multi-stream pipeline: rescue(chunk i) overlaps GEMM(chunk i+1).
// Stream/event handles are one-time host resources; the captured work is
// identical and deterministic on every call.
// ---------------------------------------------------------------------------
extern "C" void kernel_launch(void* const* d_in, const int* in_sizes, int n_in,
                              void* d_out, int out_size) {
    const float* X = (const float*)d_in[0];
    const float* E = (const float*)d_in[1];
    float* out = (float*)d_out;

    static cudaStream_t s1 = nullptr;
    static cudaEvent_t  evG[NCHUNK_PIPE];
    static cudaEvent_t  evJoin = nullptr;
    if (s1 == nullptr) {
        cudaStreamCreateWithFlags(&s1, cudaStreamNonBlocking);
        for (int i = 0; i < NCHUNK_PIPE; i++)
            cudaEventCreateWithFlags(&evG[i], cudaEventDisableTiming);
        cudaEventCreateWithFlags(&evJoin, cudaEventDisableTiming);
        cudaFuncSetAttribute(vq_mma_kernel,
                             cudaFuncAttributeMaxDynamicSharedMemorySize, SMEM_BYTES);
    }

    int warps = KCODE + NROWS;
    prep_kernel<<<(warps * 32 + 255) / 256, 256>>>(X, E);

    for (int i = 0; i < NCHUNK_PIPE; i++) {
        vq_mma_kernel<<<RT_PER_CHUNK * NCT, 256, SMEM_BYTES>>>(i * ROWS_PER_CHUNK);
        cudaEventRecord(evG[i], 0);                       // fork point
        cudaStreamWaitEvent(s1, evG[i], 0);
        rescue_gather_kernel<<<ROWS_PER_CHUNK * 32 / 256, 256, 0, s1>>>(
            X, E, out, i * ROWS_PER_CHUNK);
    }
    cudaEventRecord(evJoin, s1);                          // join side stream
    cudaStreamWaitEvent(0, evJoin, 0);
}

// round 17
// speedup vs baseline: 2.0914x; 1.5343x over previous
#include <cuda_runtime.h>
#include <cuda_bf16.h>
#include <cuda_fp16.h>
#include <math_constants.h>
#include <cstdint>

// Shapes: latents [16,2048,512] -> [32768,512], embedding [8192,512]
constexpr int DDIM  = 512;
constexpr int KCODE = 8192;
constexpr int NROWS = 16 * 2048;

constexpr int TM = 128;
constexpr int TN = 128;
constexpr int KB = 64;           // bf16 elems per stage row = 128B
constexpr int NSTAGE = 3;
constexpr int NKS = DDIM / KB;   // 8
constexpr int NRT = NROWS / TM;  // 256
constexpr int NCT = KCODE / TN;  // 64

constexpr int   NCAND  = 64;      // smem candidate slots (E[cnt]~2)
constexpr float MARGIN = 1.2e-3f; // bf16 worst (2.7e-4) + tie win (1.9e-4) + half ulp, 2x slack

constexpr uint32_t STAGE_BYTES = TM * KB * 2;               // 16384
constexpr uint32_t B_OFF       = NSTAGE * STAGE_BYTES;      // 49152
constexpr uint32_t SMEM_BYTES  = 2 * NSTAGE * STAGE_BYTES;  // 98304

// ---------------- scratch ----------------
__device__ __nv_bfloat16 g_Xb[NROWS * DDIM];
__device__ __nv_bfloat16 g_Eb[KCODE * DDIM];
__device__ float    g_e2[KCODE];
__device__ float    g_x2[NROWS];
__device__ __half   g_score[(size_t)NROWS * KCODE];   // 512 MB approx scores
__device__ unsigned g_rowmin[NROWS];                  // float-ordered keys

// ---------------- helpers ----------------
__device__ __forceinline__ uint32_t smem_u32(const void* p) {
    uint32_t a;
    asm("{ .reg .u64 t; cvta.to.shared.u64 t, %1; cvt.u32.u64 %0, t; }" : "=r"(a) : "l"(p));
    return a;
}
__device__ __forceinline__ unsigned fkey(float f) {          // order-preserving
    unsigned b = __float_as_uint(f);
    return b ^ (unsigned)(((int)b >> 31) | 0x80000000);
}
__device__ __forceinline__ float funkey(unsigned k) {
    unsigned b = k ^ (unsigned)((~(int)k >> 31) | 0x80000000);
    return __uint_as_float(b);
}
__device__ __forceinline__ void mma16(float* d, const uint32_t* a, const uint32_t* b) {
    asm volatile(
        "mma.sync.aligned.m16n8k16.row.col.f32.bf16.bf16.f32 "
        "{%0,%1,%2,%3}, {%4,%5,%6,%7}, {%8,%9}, {%0,%1,%2,%3};"
        : "+f"(d[0]), "+f"(d[1]), "+f"(d[2]), "+f"(d[3])
        : "r"(a[0]), "r"(a[1]), "r"(a[2]), "r"(a[3]), "r"(b[0]), "r"(b[1]));
}
#define LDSM_X4(r0, r1, r2, r3, addr)                                            \
    asm volatile("ldmatrix.sync.aligned.m8n8.x4.shared.b16 {%0,%1,%2,%3}, [%4];" \
        : "=r"(r0), "=r"(r1), "=r"(r2), "=r"(r3) : "r"(addr))
#define CP_ASYNC16(dst, src) \
    asm volatile("cp.async.cg.shared.global [%0], [%1], 16;" :: "r"(dst), "l"(src) : "memory")
#define CP_COMMIT()  asm volatile("cp.async.commit_group;" ::: "memory")
#define CP_WAIT1()   asm volatile("cp.async.wait_group 1;" ::: "memory")

// ---------------------------------------------------------------------------
// Kernel 1: norms (R1-proven structure) + bf16 convert + rowmin init
// ---------------------------------------------------------------------------
__global__ void prep_kernel(const float* __restrict__ X, const float* __restrict__ E) {
    int w    = (blockIdx.x * blockDim.x + threadIdx.x) >> 5;
    int lane = threadIdx.x & 31;
    if (w >= KCODE + NROWS) return;
    bool isE = (w < KCODE);
    int  r   = isE ? w : (w - KCODE);
    const float4* p = (const float4*)(isE ? (E + (size_t)r * DDIM) : (X + (size_t)r * DDIM));

    float s = 0.f;
#pragma unroll
    for (int i = 0; i < 4; i++) {
        float4 v = p[lane + 32 * i];
        s += v.x * v.x + v.y * v.y + v.z * v.z + v.w * v.w;
    }
#pragma unroll
    for (int o = 16; o > 0; o >>= 1) s += __shfl_xor_sync(0xffffffffu, s, o);
    if (lane == 0) {
        if (isE) g_e2[r] = s;
        else { g_x2[r] = s; g_rowmin[r] = 0xFFFFFFFFu; }
    }

    __nv_bfloat162* dst = (__nv_bfloat162*)((isE ? g_Eb : g_Xb) + (size_t)r * DDIM);
#pragma unroll
    for (int i = 0; i < 4; i++) {
        float4 v = p[lane + 32 * i];
        dst[(lane + 32 * i) * 2 + 0] = __floats2bfloat162_rn(v.x, v.y);
        dst[(lane + 32 * i) * 2 + 1] = __floats2bfloat162_rn(v.z, v.w);
    }
}

// ---------------------------------------------------------------------------
// Kernel 2: bf16 GEMM (128x128 tile, K=512) via ldmatrix + mma.sync.
// Byte-identical to the best-measured R7 kernel.
// ---------------------------------------------------------------------------
__global__ __launch_bounds__(256, 2) void vq_mma_kernel() {
    extern __shared__ char smem[];
    const uint32_t sb = smem_u32(smem);
    const int tid = threadIdx.x;
    const int wid = tid >> 5, lane = tid & 31;
    const int g = lane >> 2, tig = lane & 3;
    const int wm = wid & 3, wn = wid >> 2;          // warp grid 4 x 2
    const int rt = blockIdx.x >> 6;                 // col-tile fastest (L2 reuse)
    const int ct = blockIdx.x & 63;
    const int row0 = rt * TM;
    const int col0 = ct * TN;

    auto stage_cp = [&](int s, int ks) {
#pragma unroll
        for (int i = 0; i < 4; i++) {               // A: 1024 16B chunks
            int u = tid + 256 * i, row = u >> 3, c = u & 7;
            const void* src = g_Xb + (size_t)(row0 + row) * DDIM + ks + c * 8;
            uint32_t dst = sb + (uint32_t)s * STAGE_BYTES +
                           (uint32_t)(row * 128 + (c ^ (row & 7)) * 16);
            CP_ASYNC16(dst, src);
        }
#pragma unroll
        for (int i = 0; i < 4; i++) {               // B: 1024 16B chunks
            int u = tid + 256 * i, row = u >> 3, c = u & 7;
            const void* src = g_Eb + (size_t)(col0 + row) * DDIM + ks + c * 8;
            uint32_t dst = sb + B_OFF + (uint32_t)s * STAGE_BYTES +
                           (uint32_t)(row * 128 + (c ^ (row & 7)) * 16);
            CP_ASYNC16(dst, src);
        }
    };

    const int lrow = lane & 7, sel = lane >> 3;
    int arow[2]; const int acb = sel >> 1;
#pragma unroll
    for (int mt = 0; mt < 2; mt++) arow[mt] = wm * 32 + mt * 16 + lrow + (sel & 1) * 8;
    int brow[4]; const int bcb = sel & 1;
#pragma unroll
    for (int ntp = 0; ntp < 4; ntp++) brow[ntp] = wn * 64 + ntp * 16 + (sel >> 1) * 8 + lrow;

    float acc[2][8][4];
#pragma unroll
    for (int mt = 0; mt < 2; mt++)
#pragma unroll
        for (int nt = 0; nt < 8; nt++)
#pragma unroll
            for (int q = 0; q < 4; q++) acc[mt][nt][q] = 0.f;

    stage_cp(0, 0);  CP_COMMIT();
    stage_cp(1, KB); CP_COMMIT();

    for (int ks = 0; ks < NKS; ks++) {
        CP_WAIT1();
        __syncthreads();
        if (ks < NKS - 2) stage_cp((ks + 2) % NSTAGE, (ks + 2) * KB);
        CP_COMMIT();

        const int buf = ks % NSTAGE;
        const uint32_t As = sb + (uint32_t)buf * STAGE_BYTES;
        const uint32_t Bs = sb + B_OFF + (uint32_t)buf * STAGE_BYTES;

#pragma unroll
        for (int s16 = 0; s16 < 4; s16++) {
            uint32_t a[2][4];
#pragma unroll
            for (int mt = 0; mt < 2; mt++) {
                int c = 2 * s16 + acb;
                uint32_t ad = As + arow[mt] * 128 + ((c ^ (arow[mt] & 7)) * 16);
                LDSM_X4(a[mt][0], a[mt][1], a[mt][2], a[mt][3], ad);
            }
            uint32_t b[8][2];
#pragma unroll
            for (int ntp = 0; ntp < 4; ntp++) {
                int c = 2 * s16 + bcb;
                uint32_t bd = Bs + brow[ntp] * 128 + ((c ^ (brow[ntp] & 7)) * 16);
                LDSM_X4(b[2 * ntp][0], b[2 * ntp][1], b[2 * ntp + 1][0], b[2 * ntp + 1][1], bd);
            }
#pragma unroll
            for (int nt = 0; nt < 8; nt++) {
                mma16(acc[0][nt], a[0], b[nt]);
                mma16(acc[1][nt], a[1], b[nt]);
            }
        }
    }

    // ---- epilogue: score = e2 - 2*dot -> fp16 store + per-row atomic min ----
#pragma unroll
    for (int mt = 0; mt < 2; mt++) {
#pragma unroll
        for (int rr = 0; rr < 2; rr++) {
            int row = row0 + wm * 32 + mt * 16 + g + rr * 8;
            __half* srow = g_score + ((size_t)row << 13);
            float rmin = CUDART_INF_F;
#pragma unroll
            for (int nt = 0; nt < 8; nt++) {
                int col = col0 + wn * 64 + nt * 8 + 2 * tig;
                float s0 = __ldg(&g_e2[col])     - 2.0f * acc[mt][nt][rr * 2];
                float s1 = __ldg(&g_e2[col + 1]) - 2.0f * acc[mt][nt][rr * 2 + 1];
                rmin = fminf(rmin, fminf(s0, s1));
                *(__half2*)(srow + col) = __floats2half2_rn(s0, s1);
            }
            rmin = fminf(rmin, __shfl_xor_sync(0xffffffffu, rmin, 1));
            rmin = fminf(rmin, __shfl_xor_sync(0xffffffffu, rmin, 2));
            if (tig == 0) atomicMin(&g_rowmin[row], fkey(rmin));
        }
    }
}

// ---------------------------------------------------------------------------
// Kernel 3: BLOCK-per-row rescue + fused gather/STE. 256 threads scan the
// row's 16KB of scores in 4 unrolled loads each (MLP=4); hits go to a smem
// candidate list; warp 0 runs the byte-identical exact-dist form per
// candidate (one per lane); all threads gather/STE. Overflow -> full exact
// scan fallback.
// ---------------------------------------------------------------------------
__global__ __launch_bounds__(256) void rescue_gather_kernel(
    const float* __restrict__ X, const float* __restrict__ E,
    float* __restrict__ out) {
    const int row = blockIdx.x;
    const int tid = threadIdx.x, wid = tid >> 5, lane = tid & 31;

    __shared__ int s_cnt;
    __shared__ int s_cand[NCAND];
    __shared__ unsigned long long s_best;
    if (tid == 0) s_cnt = 0;
    __syncthreads();

    const uint4* sv = (const uint4*)(g_score + ((size_t)row << 13));
    const float Tf = funkey(g_rowmin[row]) + MARGIN;

    // ---- scan: 1024 uint4 = 16KB, 4 per thread, unrolled (independent) ----
    uint4 v[4];
#pragma unroll
    for (int it = 0; it < 4; it++) v[it] = __ldg(&sv[tid + 256 * it]);
#pragma unroll
    for (int it = 0; it < 4; it++) {
        __half2 h0 = *(__half2*)&v[it].x, h1 = *(__half2*)&v[it].y;
        __half2 h2 = *(__half2*)&v[it].z, h3 = *(__half2*)&v[it].w;
        __half2 mn2 = __hmin2(__hmin2(h0, h1), __hmin2(h2, h3));
        float mn = fminf(__low2float(mn2), __high2float(mn2));
        if (mn <= Tf) {                                // rare
            const __half2 hh[4] = {h0, h1, h2, h3};
#pragma unroll
            for (int q = 0; q < 4; q++) {
                float2 f = __half22float2(hh[q]);
                float sc2[2] = {f.x, f.y};
#pragma unroll
                for (int e = 0; e < 2; e++) {
                    if (sc2[e] <= Tf) {
                        int idx = atomicAdd(&s_cnt, 1);
                        if (idx < NCAND)
                            s_cand[idx] = (tid + 256 * it) * 8 + q * 2 + e;
                    }
                }
            }
        }
    }
    __syncthreads();

    const float x2v = g_x2[row];
    const float* xr = X + (size_t)row * DDIM;

    if (wid == 0) {
        unsigned long long best = ~0ull;
        if (s_cnt > NCAND) {
            // overflow fallback: exact scan of all codes (correct, ~never taken)
            for (int k = lane; k < KCODE; k += 32) {
                const float* er = E + (size_t)k * DDIM;
                float acc = 0.f;
                for (int d = 0; d < DDIM; d++) acc += xr[d] * er[d];
                float t    = x2v + g_e2[k];
                float dist = t - 2.0f * acc;
                unsigned long long p =
                    ((unsigned long long)__float_as_uint(dist) << 32) | (unsigned)k;
                best = (p < best) ? p : best;
            }
        } else {
            for (int i = lane; i < s_cnt; i += 32) {
                int k = s_cand[i];
                const float* er = E + (size_t)k * DDIM;
                float acc = 0.f;
                for (int d = 0; d < DDIM; d++) acc += xr[d] * er[d];
                float t    = x2v + g_e2[k];
                float dist = t - 2.0f * acc;           // exact R1-form dist
                unsigned long long p =
                    ((unsigned long long)__float_as_uint(dist) << 32) | (unsigned)k;
                best = (p < best) ? p : best;
            }
        }
#pragma unroll
        for (int o = 16; o > 0; o >>= 1) {
            unsigned long long q = __shfl_xor_sync(0xffffffffu, best, o);
            best = (q < best) ? q : best;
        }
        if (lane == 0) s_best = best;
    }
    __syncthreads();
    const int c = (int)(unsigned)(s_best & 0xffffffffull);

    // fused gather + STE rounding: out = x + (e - x); 128 float4s per row
    if (tid < 128) {
        float4 e = ((const float4*)(E + (size_t)c * DDIM))[tid];
        float4 x = ((const float4*)xr)[tid];
        float4 o;
        o.x = __fadd_rn(x.x, __fsub_rn(e.x, x.x));
        o.y = __fadd_rn(x.y, __fsub_rn(e.y, x.y));
        o.z = __fadd_rn(x.z, __fsub_rn(e.z, x.z));
        o.w = __fadd_rn(x.w, __fsub_rn(e.w, x.w));
        ((float4*)(out + (size_t)row * DDIM))[tid] = o;
    }
}

// ---------------------------------------------------------------------------
extern "C" void kernel_launch(void* const* d_in, const int* in_sizes, int n_in,
                              void* d_out, int out_size) {
    const float* X = (const float*)d_in[0];
    const float* E = (const float*)d_in[1];
    float* out = (float*)d_out;

    cudaFuncSetAttribute(vq_mma_kernel, cudaFuncAttributeMaxDynamicSharedMemorySize,
                         SMEM_BYTES);

    int warps = KCODE + NROWS;
    prep_kernel<<<(warps * 32 + 255) / 256, 256>>>(X, E);
    vq_mma_kernel<<<NRT * NCT, 256, SMEM_BYTES>>>();
    rescue_gather_kernel<<<NROWS, 256>>>(X, E, out);
}